// round 10
// baseline (speedup 1.0000x reference)
#include <cuda_runtime.h>
#include <cuda_bf16.h>
#include <cstddef>
#include <cstdint>

#define SEQ   2048
#define BATCH 64
#define NIN   256
#define HID   256

#define RNN_BLOCKS   64                  // one CTA per batch element
#define PROJ_TILES_N 4                   // 256 / 64
#define PROJ_CHUNKS  1024                // 131072 / 128 m-rows; chunk = 2 steps
#define PROJ_BLOCKS  (PROJ_CHUNKS * PROJ_TILES_N)
#define TOTAL_BLOCKS (RNN_BLOCKS + PROJ_BLOCKS)   // 4160

// dynamic smem layout (floats):
//   rnn : wsh[512][36] | hbuf[2][256] | ps[256][2]
//   proj: As[32][132]  | Bs[32][68]
#define SM_WSH_F   (512 * 36)
#define SM_H_F     (2 * 256)
#define SM_PS_F    (256 * 2)
#define SM_TOTAL_B ((SM_WSH_F + SM_H_F + SM_PS_F) * 4)

// Scratch
__device__ float g_xp[(size_t)SEQ * BATCH * HID];
__device__ int   g_done[PROJ_CHUNKS];

// ---------------------------------------------------------------------------
// helpers
// ---------------------------------------------------------------------------
#define FMA2(acc, a, b)                                             \
    asm("fma.rn.f32x2 %0, %1, %2, %3;"                              \
        : "=l"(acc) : "l"(a), "l"(b), "l"(acc))

__device__ __forceinline__ unsigned long long pack_dup(float x) {
    unsigned long long d;
    asm("mov.b64 %0, {%1, %1};" : "=l"(d) : "r"(__float_as_uint(x)));
    return d;
}
__device__ __forceinline__ float2 unpack2(unsigned long long v) {
    float2 r;
    asm("mov.b64 {%0, %1}, %2;" : "=f"(r.x), "=f"(r.y) : "l"(v));
    return r;
}
__device__ __forceinline__ int ld_acquire_gpu(const int* p) {
    int v;
    asm volatile("ld.acquire.gpu.b32 %0, [%1];" : "=r"(v) : "l"(p) : "memory");
    return v;
}
// fast tanh: 1 - 2/(e^{2x}+1), MUFU-based, ~1e-6 rel err, saturates correctly.
__device__ __forceinline__ float ftanh(float x) {
    float e = __expf(2.f * x);
    return 1.f - __fdividef(2.f, e + 1.f);
}

// ---------------------------------------------------------------------------
// reset kernel: zero proj-completion flags (each graph replay)
// ---------------------------------------------------------------------------
__global__ void reset_kernel() {
    for (int i = threadIdx.x; i < PROJ_CHUNKS; i += blockDim.x) g_done[i] = 0;
}

// ---------------------------------------------------------------------------
// Fused kernel, 512 threads/CTA, NO clusters.
//   blocks [0,64): recurrence, one CTA per batch. Thread t: row = t&255,
//     k-chunk c = t>>8 (128 k's). 96 weight-floats in regs + 32 in smem
//     (crossbar 64KB/step = 512cyc, overlapping the 512cyc FMA floor).
//     h (256 floats) is CTA-local, double-buffered; 2 bar.sync per step.
//   blocks [64,4160): projection GEMM tiles (BM=128,BN=64,BK=32) at 512
//     threads; n-tile fastest; finished m-chunk (=2 timesteps) bumps
//     g_done[chunk] (release); rnn gates xp prefetch on it (R3-proven).
// ---------------------------------------------------------------------------
__global__ void __launch_bounds__(512, 1)
fused_kernel(const float* __restrict__ X,
             const float* __restrict__ W_ih,
             const float* __restrict__ W_hh,
             const float* __restrict__ b_ih,
             const float* __restrict__ b_hh,
             float* __restrict__ out)
{
    extern __shared__ float dsm[];
    const int t = threadIdx.x;

    if (blockIdx.x >= RNN_BLOCKS) {
        // ===================== PROJECTION PATH =====================
        float (*As)[132] = (float (*)[132])dsm;
        float (*Bs)[68]  = (float (*)[68])(dsm + 32 * 132);

        const int pb    = blockIdx.x - RNN_BLOCKS;
        const int chunk = pb >> 2;                 // m-chunk (slow)
        const int ntile = pb & 3;                  // n-tile  (fast)
        const int m0    = chunk * 128;
        const int n0    = ntile * 64;
        const int tx    = t & 15;                  // n group (4 each)
        const int ty    = t >> 4;                  // m group 0..31 (4 each)

        unsigned long long acc2[2][4];             // [m-pair][n]
#pragma unroll
        for (int i = 0; i < 2; i++)
#pragma unroll
            for (int j = 0; j < 4; j++) acc2[i][j] = 0ULL;

        for (int kb = 0; kb < NIN; kb += 32) {
            // A tile: 128x32 = 1024 float4, 2 per thread
#pragma unroll
            for (int it = 0; it < 2; it++) {
                int idx = t + it * 512;
                int r   = idx >> 3;
                int c4  = idx & 7;
                float4 v = *(const float4*)&X[(size_t)(m0 + r) * NIN + kb + c4 * 4];
                As[c4 * 4 + 0][r] = v.x;
                As[c4 * 4 + 1][r] = v.y;
                As[c4 * 4 + 2][r] = v.z;
                As[c4 * 4 + 3][r] = v.w;
            }
            // B tile: 64x32 = 512 float4, 1 per thread
            {
                int r  = t >> 3;
                int c4 = t & 7;
                float4 v = *(const float4*)&W_ih[(size_t)(n0 + r) * NIN + kb + c4 * 4];
                Bs[c4 * 4 + 0][r] = v.x;
                Bs[c4 * 4 + 1][r] = v.y;
                Bs[c4 * 4 + 2][r] = v.z;
                Bs[c4 * 4 + 3][r] = v.w;
            }
            __syncthreads();
#pragma unroll
            for (int k = 0; k < 32; k++) {
                ulonglong2 av = *(const ulonglong2*)&As[k][ty * 4];
                float4 bv = *(const float4*)&Bs[k][tx * 4];
                unsigned long long bd0 = pack_dup(bv.x);
                unsigned long long bd1 = pack_dup(bv.y);
                unsigned long long bd2 = pack_dup(bv.z);
                unsigned long long bd3 = pack_dup(bv.w);
                FMA2(acc2[0][0], av.x, bd0); FMA2(acc2[0][1], av.x, bd1);
                FMA2(acc2[0][2], av.x, bd2); FMA2(acc2[0][3], av.x, bd3);
                FMA2(acc2[1][0], av.y, bd0); FMA2(acc2[1][1], av.y, bd1);
                FMA2(acc2[1][2], av.y, bd2); FMA2(acc2[1][3], av.y, bd3);
            }
            __syncthreads();
        }

        const int nbase = n0 + tx * 4;
        float4 bias;
        bias.x = b_ih[nbase + 0] + b_hh[nbase + 0];
        bias.y = b_ih[nbase + 1] + b_hh[nbase + 1];
        bias.z = b_ih[nbase + 2] + b_hh[nbase + 2];
        bias.w = b_ih[nbase + 3] + b_hh[nbase + 3];
#pragma unroll
        for (int mi = 0; mi < 2; mi++) {
            float2 c0 = unpack2(acc2[mi][0]);
            float2 c1 = unpack2(acc2[mi][1]);
            float2 c2 = unpack2(acc2[mi][2]);
            float2 c3 = unpack2(acc2[mi][3]);
            int mA = m0 + ty * 4 + 2 * mi;
            float4 v0 = { c0.x + bias.x, c1.x + bias.y, c2.x + bias.z, c3.x + bias.w };
            float4 v1 = { c0.y + bias.x, c1.y + bias.y, c2.y + bias.z, c3.y + bias.w };
            *(float4*)&g_xp[(size_t)mA * HID + nbase]       = v0;
            *(float4*)&g_xp[(size_t)(mA + 1) * HID + nbase] = v1;
        }

        __syncthreads();
        if (t == 0) {
            __threadfence();
            atomicAdd(&g_done[chunk], 1);
        }
        return;
    }

    // ===================== RECURRENCE PATH =====================
    float* wsh  = dsm;                          // [512][36]
    float* hbuf = dsm + SM_WSH_F;               // [2][256]
    float* ps   = dsm + SM_WSH_F + SM_H_F;      // [256][2]

    const int b     = blockIdx.x;
    const int row   = t & 255;
    const int c     = t >> 8;                   // 0 or 1
    const int kbase = c << 7;

    // weights: W_hh[row][kbase .. kbase+96) -> 48 u64 regs,
    //          W_hh[row][kbase+96 .. +128)  -> smem (32 floats, stride 36)
    unsigned long long wr[48];
    {
        const ulonglong2* wp =
            (const ulonglong2*)(W_hh + (size_t)row * HID + kbase);
#pragma unroll
        for (int i = 0; i < 24; i++) {
            ulonglong2 v = wp[i];
            wr[2 * i]     = v.x;
            wr[2 * i + 1] = v.y;
        }
        const float4* wtail =
            (const float4*)(W_hh + (size_t)row * HID + kbase + 96);
        float4* dst = (float4*)&wsh[t * 36];
#pragma unroll
        for (int i = 0; i < 8; i++) dst[i] = wtail[i];
    }

    if (t < 256) hbuf[t] = 0.f;                 // h_0 = 0 (buffer 0)
    __syncthreads();

    // initial proj-flag gate: chunks 0..17 cover xp[0..35]
    int wm = 0;
    if (t == 0) {
        while (wm <= 17) {
            if (ld_acquire_gpu(&g_done[wm]) >= PROJ_TILES_N) wm++;
        }
    }
    __syncthreads();

    // xp window (combine threads t<256, row = t)
    const float* xptr = g_xp + (size_t)b * HID + t;
    float x0 = 0.f, x1 = 0.f, x2 = 0.f;
    if (t < 256) {
        x0 = xptr[0];
        x1 = xptr[(size_t)1 * BATCH * HID];
        x2 = xptr[(size_t)2 * BATCH * HID];
    }
    float* outp = out + (size_t)b * HID + t;
    const ulonglong2* wq = (const ulonglong2*)&wsh[t * 36];

#pragma unroll 1
    for (int s = 0; s < SEQ; s++) {
        const int buf = s & 1;

        // ---- dot over this thread's 128-k chunk ----
        const ulonglong2* hp = (const ulonglong2*)(hbuf + (buf << 8) + kbase);
        unsigned long long a0 = 0ULL, a1 = 0ULL;
#pragma unroll
        for (int i = 0; i < 24; i++) {          // 96 floats from registers
            ulonglong2 hv = hp[i];
            FMA2(a0, wr[2 * i],     hv.x);
            FMA2(a1, wr[2 * i + 1], hv.y);
        }
#pragma unroll
        for (int i = 0; i < 8; i++) {           // 32 floats from smem
            ulonglong2 hv = hp[24 + i];
            ulonglong2 wv = wq[i];
            FMA2(a0, wv.x, hv.x);
            FMA2(a1, wv.y, hv.y);
        }
        float2 f0 = unpack2(a0), f1 = unpack2(a1);
        ps[(row << 1) + c] = (f0.x + f0.y) + (f1.x + f1.y);
        __syncthreads();

        // ---- combine + tanh + publish (threads 0-255, row = t) ----
        if (t < 256) {
            float2 pv = *(const float2*)&ps[t << 1];
            float hv  = ftanh((pv.x + pv.y) + x0);
            hbuf[((buf ^ 1) << 8) + t] = hv;
            outp[(size_t)s * BATCH * HID] = hv;

            x0 = x1; x1 = x2;
            x2 = (s + 3 < SEQ) ? xptr[(size_t)(s + 3) * BATCH * HID] : 0.f;
        }
        // periodic proj-flag gate
        if ((s & 15) == 0 && t == 0) {
            int need = (s + 35) >> 1;
            if (need > PROJ_CHUNKS - 1) need = PROJ_CHUNKS - 1;
            while (wm <= need) {
                if (ld_acquire_gpu(&g_done[wm]) >= PROJ_TILES_N) wm++;
            }
        }
        __syncthreads();
    }
}

// ---------------------------------------------------------------------------
extern "C" void kernel_launch(void* const* d_in, const int* in_sizes, int n_in,
                              void* d_out, int out_size)
{
    const float* input = (const float*)d_in[0];   // [SEQ, BATCH, NIN]
    const float* W_ih  = (const float*)d_in[1];   // [HID, NIN]
    const float* W_hh  = (const float*)d_in[2];   // [HID, HID]
    const float* b_ih  = (const float*)d_in[3];   // [HID]
    const float* b_hh  = (const float*)d_in[4];   // [HID]
    float* out = (float*)d_out;                   // [SEQ*BATCH, HID]

    cudaFuncSetAttribute(fused_kernel,
                         cudaFuncAttributeMaxDynamicSharedMemorySize,
                         SM_TOTAL_B);

    reset_kernel<<<1, 256>>>();
    fused_kernel<<<TOTAL_BLOCKS, 512, SM_TOTAL_B>>>(
        input, W_ih, W_hh, b_ih, b_hh, out);
}

// round 11
// speedup vs baseline: 1.2678x; 1.2678x over previous
#include <cuda_runtime.h>
#include <cuda_bf16.h>
#include <cstddef>
#include <cstdint>

#define SEQ   2048
#define BATCH 64
#define NIN   256
#define HID   256

// Scratch: x_proj[s][b][h]
__device__ float g_xp[(size_t)SEQ * BATCH * HID];

// ---------------------------------------------------------------------------
// helpers
// ---------------------------------------------------------------------------
__device__ __forceinline__ uint32_t smem_u32(const void* p) {
    uint32_t a;
    asm("{ .reg .u64 t; cvta.to.shared.u64 t, %1; cvt.u32.u64 %0, t; }"
        : "=r"(a) : "l"(p));
    return a;
}

#define FMA2(acc, a, b)                                             \
    asm("fma.rn.f32x2 %0, %1, %2, %3;"                              \
        : "=l"(acc) : "l"(a), "l"(b), "l"(acc))

__device__ __forceinline__ unsigned long long pack_dup(float x) {
    unsigned long long d;
    asm("mov.b64 %0, {%1, %1};" : "=l"(d) : "r"(__float_as_uint(x)));
    return d;
}
__device__ __forceinline__ float2 unpack2(unsigned long long v) {
    float2 r;
    asm("mov.b64 {%0, %1}, %2;" : "=f"(r.x), "=f"(r.y) : "l"(v));
    return r;
}

__device__ __forceinline__ void mbar_wait(uint32_t mbar, uint32_t parity) {
    asm volatile(
        "{\n\t"
        ".reg .pred P;\n"
        "$WL%=:\n\t"
        "mbarrier.try_wait.parity.acquire.cta.shared::cta.b64 P, [%0], %1, 0x989680;\n\t"
        "@!P bra $WL%=;\n\t"
        "}"
        :: "r"(mbar), "r"(parity) : "memory");
}

// fast tanh: 1 - 2/(e^{2x}+1), MUFU-based, ~1e-6 rel err, saturates correctly.
__device__ __forceinline__ float ftanh(float x) {
    float e = __expf(2.f * x);
    return 1.f - __fdividef(2.f, e + 1.f);
}

// ---------------------------------------------------------------------------
// Kernel 1: input projection GEMM (f32x2) — R2-proven (~370us), unchanged.
// ---------------------------------------------------------------------------
__global__ void __launch_bounds__(256) proj_kernel(
    const float* __restrict__ X,
    const float* __restrict__ W,
    const float* __restrict__ b_ih,
    const float* __restrict__ b_hh)
{
    constexpr int BM = 128, BN = 64, BK = 32;
    __shared__ float As[BK][BM + 4];
    __shared__ float Bs[BK][BN + 4];

    const int tid = threadIdx.x;
    const int m0  = blockIdx.x * BM;
    const int n0  = blockIdx.y * BN;
    const int tx  = tid & 15;
    const int ty  = tid >> 4;

    unsigned long long acc2[4][4];
#pragma unroll
    for (int i = 0; i < 4; i++)
#pragma unroll
        for (int j = 0; j < 4; j++) acc2[i][j] = 0ULL;

    for (int kb = 0; kb < NIN; kb += BK) {
#pragma unroll
        for (int it = 0; it < 4; it++) {
            int idx = tid + it * 256;
            int r   = idx >> 3;
            int c4  = idx & 7;
            float4 v = *(const float4*)&X[(size_t)(m0 + r) * NIN + kb + c4 * 4];
            As[c4 * 4 + 0][r] = v.x;
            As[c4 * 4 + 1][r] = v.y;
            As[c4 * 4 + 2][r] = v.z;
            As[c4 * 4 + 3][r] = v.w;
        }
#pragma unroll
        for (int it = 0; it < 2; it++) {
            int idx = tid + it * 256;
            int r   = idx >> 3;
            int c4  = idx & 7;
            float4 v = *(const float4*)&W[(size_t)(n0 + r) * NIN + kb + c4 * 4];
            Bs[c4 * 4 + 0][r] = v.x;
            Bs[c4 * 4 + 1][r] = v.y;
            Bs[c4 * 4 + 2][r] = v.z;
            Bs[c4 * 4 + 3][r] = v.w;
        }
        __syncthreads();

#pragma unroll
        for (int k = 0; k < BK; k++) {
            const ulonglong2* ap = (const ulonglong2*)&As[k][ty * 8];
            ulonglong2 av0 = ap[0];
            ulonglong2 av1 = ap[1];
            float4 bv = *(const float4*)&Bs[k][tx * 4];
            unsigned long long bd0 = pack_dup(bv.x);
            unsigned long long bd1 = pack_dup(bv.y);
            unsigned long long bd2 = pack_dup(bv.z);
            unsigned long long bd3 = pack_dup(bv.w);
            FMA2(acc2[0][0], av0.x, bd0); FMA2(acc2[0][1], av0.x, bd1);
            FMA2(acc2[0][2], av0.x, bd2); FMA2(acc2[0][3], av0.x, bd3);
            FMA2(acc2[1][0], av0.y, bd0); FMA2(acc2[1][1], av0.y, bd1);
            FMA2(acc2[1][2], av0.y, bd2); FMA2(acc2[1][3], av0.y, bd3);
            FMA2(acc2[2][0], av1.x, bd0); FMA2(acc2[2][1], av1.x, bd1);
            FMA2(acc2[2][2], av1.x, bd2); FMA2(acc2[2][3], av1.x, bd3);
            FMA2(acc2[3][0], av1.y, bd0); FMA2(acc2[3][1], av1.y, bd1);
            FMA2(acc2[3][2], av1.y, bd2); FMA2(acc2[3][3], av1.y, bd3);
        }
        __syncthreads();
    }

    const int nbase = n0 + tx * 4;
    float4 bias;
    bias.x = b_ih[nbase + 0] + b_hh[nbase + 0];
    bias.y = b_ih[nbase + 1] + b_hh[nbase + 1];
    bias.z = b_ih[nbase + 2] + b_hh[nbase + 2];
    bias.w = b_ih[nbase + 3] + b_hh[nbase + 3];
#pragma unroll
    for (int mi = 0; mi < 4; mi++) {
        float2 c0 = unpack2(acc2[mi][0]);
        float2 c1 = unpack2(acc2[mi][1]);
        float2 c2 = unpack2(acc2[mi][2]);
        float2 c3 = unpack2(acc2[mi][3]);
        int mA = m0 + ty * 8 + 2 * mi;
        float4 v0 = { c0.x + bias.x, c1.x + bias.y, c2.x + bias.z, c3.x + bias.w };
        float4 v1 = { c0.y + bias.x, c1.y + bias.y, c2.y + bias.z, c3.y + bias.w };
        *(float4*)&g_xp[(size_t)mA * HID + nbase]       = v0;
        *(float4*)&g_xp[(size_t)(mA + 1) * HID + nbase] = v1;
    }
}

// ---------------------------------------------------------------------------
// Kernel 2: recurrence rnn7 — the R2-proven kernel with 3 surgical changes:
//   (1) each thread sends its partial ONLY if the peer owns its row
//       (t>>7 != rank): 128 msgs/step (was 256), expect_tx 512B.
//   (2) ftanh (MUFU) replaces tanhf on the combine critical path.
//   (3) combine/tanh/out and the xp window predicated to own rows.
//   Everything else byte-identical to R2: 64 clusters x 2 CTAs (one batch
//   per cluster), 256 threads, thread t = row t over k-half [128*rank,+128)
//   with all 64 u64 weights in registers, full-h double buffer, 2 mbars
//   (bar[s&1], parity (s>>1)&1), ONE __syncthreads per step.
// ---------------------------------------------------------------------------
__global__ void __launch_bounds__(256, 1) __cluster_dims__(2, 1, 1)
rnn7_kernel(const float* __restrict__ W_hh, float* __restrict__ out)
{
    __shared__ float sm_h[2][256];        // full h (only own half ever read)
    __shared__ float sm_p[2][256];        // peer partials (own rows only)
    __shared__ __align__(8) unsigned long long sm_mbar[2];

    const int      t    = threadIdx.x;
    const uint32_t rank = blockIdx.x & 1;
    const int      b    = blockIdx.x >> 1;
    const int      k0   = rank << 7;
    const bool     own  = ((uint32_t)(t >> 7) == rank);

    // weights: W_hh[row t][k0 .. k0+127] -> 64 u64 regs
    unsigned long long w2[64];
    {
        const ulonglong2* wp = (const ulonglong2*)(W_hh + (size_t)t * HID + k0);
#pragma unroll
        for (int i = 0; i < 32; i++) {
            ulonglong2 v = wp[i];
            w2[2 * i]     = v.x;
            w2[2 * i + 1] = v.y;
        }
    }

    // h_0 = 0 (only own half is ever read by the dot)
    sm_h[0][t] = 0.f;
    sm_h[1][t] = 0.f;
    if (t == 0) {
        asm volatile("mbarrier.init.shared.b64 [%0], 1;"
                     :: "r"(smem_u32(&sm_mbar[0])) : "memory");
        asm volatile("mbarrier.init.shared.b64 [%0], 1;"
                     :: "r"(smem_u32(&sm_mbar[1])) : "memory");
    }
    __syncthreads();
    asm volatile("barrier.cluster.arrive.aligned;" ::: "memory");
    asm volatile("barrier.cluster.wait.aligned;"   ::: "memory");

    const uint32_t peer  = rank ^ 1u;
    const uint32_t p_loc = smem_u32(&sm_p[0][0]);
    const uint32_t m_loc = smem_u32(&sm_mbar[0]);
    uint32_t p_rem, m_rem;
    asm("mapa.shared::cluster.u32 %0, %1, %2;"
        : "=r"(p_rem) : "r"(p_loc), "r"(peer));
    asm("mapa.shared::cluster.u32 %0, %1, %2;"
        : "=r"(m_rem) : "r"(m_loc), "r"(peer));

    // xp window (own rows only), depth 3
    const float* xptr = g_xp + (size_t)b * HID + t;
    float x0 = 0.f, x1 = 0.f, x2 = 0.f;
    if (own) {
        x0 = xptr[0];
        x1 = xptr[(size_t)1 * BATCH * HID];
        x2 = xptr[(size_t)2 * BATCH * HID];
    }
    float* outp = out + (size_t)b * HID + t;

#pragma unroll 1
    for (int s = 0; s < SEQ; s++) {
        const uint32_t buf = (uint32_t)(s & 1);
        const uint32_t par = (uint32_t)((s >> 1) & 1);

        // ---- dot over own k-half: 32 LDS.128 + 64 FFMA2 ----
        const ulonglong2* hp = (const ulonglong2*)(&sm_h[buf][0] + k0);
        unsigned long long a0 = 0ULL, a1 = 0ULL, a2 = 0ULL, a3 = 0ULL;
#pragma unroll
        for (int i = 0; i < 16; i++) {
            ulonglong2 h01 = hp[2 * i];
            ulonglong2 h23 = hp[2 * i + 1];
            FMA2(a0, w2[4 * i + 0], h01.x);
            FMA2(a1, w2[4 * i + 1], h01.y);
            FMA2(a2, w2[4 * i + 2], h23.x);
            FMA2(a3, w2[4 * i + 3], h23.y);
        }
        float2 f0 = unpack2(a0), f1 = unpack2(a1);
        float2 f2 = unpack2(a2), f3 = unpack2(a3);
        float mine = ((f0.x + f0.y) + (f1.x + f1.y))
                   + ((f2.x + f2.y) + (f3.x + f3.y));

        // ---- send partial ONLY for peer-owned rows (128 msgs) ----
        if (!own) {
            asm volatile(
                "st.async.shared::cluster.mbarrier::complete_tx::bytes.b32 "
                "[%0], %1, [%2];"
                :: "r"(p_rem + (buf << 10) + ((uint32_t)t << 2)),
                   "r"(__float_as_uint(mine)),
                   "r"(m_rem + buf * 8u)
                : "memory");
        }
        if (t == 0)
            asm volatile("mbarrier.arrive.expect_tx.shared.b64 _, [%0], 512;"
                         :: "r"(m_loc + buf * 8u) : "memory");

        // prefetch xp[s+3] before the wait (independent work)
        float xn = 0.f;
        if (own && s + 3 < SEQ) xn = xptr[(size_t)(s + 3) * BATCH * HID];

        mbar_wait(m_loc + buf * 8u, par);

        // ---- combine + tanh + publish (own rows only) ----
        if (own) {
            float theirs = sm_p[buf][t];
            float lo = rank ? theirs : mine;
            float hi = rank ? mine   : theirs;
            float hv = ftanh(x0 + (lo + hi));
            sm_h[buf ^ 1u][t] = hv;
            outp[(size_t)s * BATCH * HID] = hv;

            x0 = x1; x1 = x2; x2 = xn;
        }
        __syncthreads();   // sm_h[buf^1] own half visible to all threads
    }

    asm volatile("barrier.cluster.arrive.aligned;" ::: "memory");
    asm volatile("barrier.cluster.wait.aligned;"   ::: "memory");
}

// ---------------------------------------------------------------------------
extern "C" void kernel_launch(void* const* d_in, const int* in_sizes, int n_in,
                              void* d_out, int out_size)
{
    const float* input = (const float*)d_in[0];   // [SEQ, BATCH, NIN]
    const float* W_ih  = (const float*)d_in[1];   // [HID, NIN]
    const float* W_hh  = (const float*)d_in[2];   // [HID, HID]
    const float* b_ih  = (const float*)d_in[3];   // [HID]
    const float* b_hh  = (const float*)d_in[4];   // [HID]
    float* out = (float*)d_out;                   // [SEQ*BATCH, HID]

    // 1) projection (full chip)
    dim3 pgrid((SEQ * BATCH) / 128, HID / 64);
    proj_kernel<<<pgrid, 256>>>(input, W_ih, b_ih, b_hh);

    // 2) recurrence: 64 clusters x 2 CTAs, one batch per cluster
    rnn7_kernel<<<BATCH * 2, 256>>>(W_hh, out);
}

// round 12
// speedup vs baseline: 1.7648x; 1.3920x over previous
#include <cuda_runtime.h>
#include <cuda_bf16.h>
#include <cstddef>
#include <cstdint>

#define SEQ   2048
#define BATCH 64
#define NIN   256
#define HID   256

#define RNN_BLOCKS  128                 // 64 clusters x 2 CTAs
#define HEAD_CHUNKS 704                 // chunks done by the head kernel
#define PROJ_CHUNKS 1024                // 131072 / 128 m-rows; 1 chunk = 2 steps
#define TAIL_CHUNKS (PROJ_CHUNKS - HEAD_CHUNKS)        // 320
#define TOTAL_BLOCKS (RNN_BLOCKS + TAIL_CHUNKS * 4)    // 1408 (even)

// Scratch
__device__ float g_xp[(size_t)SEQ * BATCH * HID];
__device__ int   g_done[PROJ_CHUNKS];

// ---------------------------------------------------------------------------
// helpers
// ---------------------------------------------------------------------------
__device__ __forceinline__ uint32_t smem_u32(const void* p) {
    uint32_t a;
    asm("{ .reg .u64 t; cvta.to.shared.u64 t, %1; cvt.u32.u64 %0, t; }"
        : "=r"(a) : "l"(p));
    return a;
}

#define FMA2(acc, a, b)                                             \
    asm("fma.rn.f32x2 %0, %1, %2, %3;"                              \
        : "=l"(acc) : "l"(a), "l"(b), "l"(acc))

__device__ __forceinline__ unsigned long long pack_dup(float x) {
    unsigned long long d;
    asm("mov.b64 %0, {%1, %1};" : "=l"(d) : "r"(__float_as_uint(x)));
    return d;
}
__device__ __forceinline__ float2 unpack2(unsigned long long v) {
    float2 r;
    asm("mov.b64 {%0, %1}, %2;" : "=f"(r.x), "=f"(r.y) : "l"(v));
    return r;
}

__device__ __forceinline__ void mbar_wait(uint32_t mbar, uint32_t parity) {
    asm volatile(
        "{\n\t"
        ".reg .pred P;\n"
        "$WL%=:\n\t"
        "mbarrier.try_wait.parity.acquire.cta.shared::cta.b64 P, [%0], %1, 0x989680;\n\t"
        "@!P bra $WL%=;\n\t"
        "}"
        :: "r"(mbar), "r"(parity) : "memory");
}

__device__ __forceinline__ int ld_acquire_gpu(const int* p) {
    int v;
    asm volatile("ld.acquire.gpu.b32 %0, [%1];" : "=r"(v) : "l"(p) : "memory");
    return v;
}

// ---------------------------------------------------------------------------
// reset kernel: zero proj-completion flags (each graph replay)
// ---------------------------------------------------------------------------
__global__ void reset_kernel() {
    for (int i = threadIdx.x; i < PROJ_CHUNKS; i += blockDim.x) g_done[i] = 0;
}

// ---------------------------------------------------------------------------
// Kernel 1: input projection GEMM (f32x2) — R2-proven body. Used for the
//   HEAD: grid (HEAD_CHUNKS, 4), full chip, own tight register allocation.
// ---------------------------------------------------------------------------
__global__ void __launch_bounds__(256) proj_kernel(
    const float* __restrict__ X,
    const float* __restrict__ W,
    const float* __restrict__ b_ih,
    const float* __restrict__ b_hh)
{
    constexpr int BM = 128, BN = 64, BK = 32;
    __shared__ float As[BK][BM + 4];
    __shared__ float Bs[BK][BN + 4];

    const int tid = threadIdx.x;
    const int m0  = blockIdx.x * BM;
    const int n0  = blockIdx.y * BN;
    const int tx  = tid & 15;
    const int ty  = tid >> 4;

    unsigned long long acc2[4][4];
#pragma unroll
    for (int i = 0; i < 4; i++)
#pragma unroll
        for (int j = 0; j < 4; j++) acc2[i][j] = 0ULL;

    for (int kb = 0; kb < NIN; kb += BK) {
#pragma unroll
        for (int it = 0; it < 4; it++) {
            int idx = tid + it * 256;
            int r   = idx >> 3;
            int c4  = idx & 7;
            float4 v = *(const float4*)&X[(size_t)(m0 + r) * NIN + kb + c4 * 4];
            As[c4 * 4 + 0][r] = v.x;
            As[c4 * 4 + 1][r] = v.y;
            As[c4 * 4 + 2][r] = v.z;
            As[c4 * 4 + 3][r] = v.w;
        }
#pragma unroll
        for (int it = 0; it < 2; it++) {
            int idx = tid + it * 256;
            int r   = idx >> 3;
            int c4  = idx & 7;
            float4 v = *(const float4*)&W[(size_t)(n0 + r) * NIN + kb + c4 * 4];
            Bs[c4 * 4 + 0][r] = v.x;
            Bs[c4 * 4 + 1][r] = v.y;
            Bs[c4 * 4 + 2][r] = v.z;
            Bs[c4 * 4 + 3][r] = v.w;
        }
        __syncthreads();

#pragma unroll
        for (int k = 0; k < BK; k++) {
            const ulonglong2* ap = (const ulonglong2*)&As[k][ty * 8];
            ulonglong2 av0 = ap[0];
            ulonglong2 av1 = ap[1];
            float4 bv = *(const float4*)&Bs[k][tx * 4];
            unsigned long long bd0 = pack_dup(bv.x);
            unsigned long long bd1 = pack_dup(bv.y);
            unsigned long long bd2 = pack_dup(bv.z);
            unsigned long long bd3 = pack_dup(bv.w);
            FMA2(acc2[0][0], av0.x, bd0); FMA2(acc2[0][1], av0.x, bd1);
            FMA2(acc2[0][2], av0.x, bd2); FMA2(acc2[0][3], av0.x, bd3);
            FMA2(acc2[1][0], av0.y, bd0); FMA2(acc2[1][1], av0.y, bd1);
            FMA2(acc2[1][2], av0.y, bd2); FMA2(acc2[1][3], av0.y, bd3);
            FMA2(acc2[2][0], av1.x, bd0); FMA2(acc2[2][1], av1.x, bd1);
            FMA2(acc2[2][2], av1.x, bd2); FMA2(acc2[2][3], av1.x, bd3);
            FMA2(acc2[3][0], av1.y, bd0); FMA2(acc2[3][1], av1.y, bd1);
            FMA2(acc2[3][2], av1.y, bd2); FMA2(acc2[3][3], av1.y, bd3);
        }
        __syncthreads();
    }

    const int nbase = n0 + tx * 4;
    float4 bias;
    bias.x = b_ih[nbase + 0] + b_hh[nbase + 0];
    bias.y = b_ih[nbase + 1] + b_hh[nbase + 1];
    bias.z = b_ih[nbase + 2] + b_hh[nbase + 2];
    bias.w = b_ih[nbase + 3] + b_hh[nbase + 3];
#pragma unroll
    for (int mi = 0; mi < 4; mi++) {
        float2 c0 = unpack2(acc2[mi][0]);
        float2 c1 = unpack2(acc2[mi][1]);
        float2 c2 = unpack2(acc2[mi][2]);
        float2 c3 = unpack2(acc2[mi][3]);
        int mA = m0 + ty * 8 + 2 * mi;
        float4 v0 = { c0.x + bias.x, c1.x + bias.y, c2.x + bias.z, c3.x + bias.w };
        float4 v1 = { c0.y + bias.x, c1.y + bias.y, c2.y + bias.z, c3.y + bias.w };
        *(float4*)&g_xp[(size_t)mA * HID + nbase]       = v0;
        *(float4*)&g_xp[(size_t)(mA + 1) * HID + nbase] = v1;
    }
}

// ---------------------------------------------------------------------------
// Kernel 2 (fused): blocks [0,128) = the R2 rnn VERBATIM (64 clusters x 2
//   CTAs, one batch each, 0.55us/step proven) + a t0-only flag gate
//   (R3-proven) for xp chunks >= HEAD_CHUNKS.
//   blocks [128, 1408): projection TAIL tiles for chunks [704, 1024) on the
//   ~20 SMs the rnn leaves free; each finished chunk (4 n-tiles) bumps
//   g_done[chunk] with a release pattern.
// ---------------------------------------------------------------------------
__global__ void __launch_bounds__(256, 1) __cluster_dims__(2, 1, 1)
fused_kernel(const float* __restrict__ X,
             const float* __restrict__ W_ih,
             const float* __restrict__ W_hh,
             const float* __restrict__ b_ih,
             const float* __restrict__ b_hh,
             float* __restrict__ out)
{
    __shared__ float sm_h[2][256];        // rnn: double-buffered h
    __shared__ float sm_p[2][256];        // rnn: peer partials
    __shared__ __align__(8) unsigned long long sm_mbar[2];
    __shared__ float sm_As[32][132];      // proj tail tiles
    __shared__ float sm_Bs[32][68];

    const int t = threadIdx.x;

    if (blockIdx.x >= RNN_BLOCKS) {
        // ===================== PROJECTION TAIL =====================
        const int pb    = blockIdx.x - RNN_BLOCKS;
        const int chunk = HEAD_CHUNKS + (pb >> 2);   // ascending completion
        const int ntile = pb & 3;
        const int m0    = chunk * 128;
        const int n0    = ntile * 64;
        const int tx    = t & 15;
        const int ty    = t >> 4;

        unsigned long long acc2[4][4];
#pragma unroll
        for (int i = 0; i < 4; i++)
#pragma unroll
            for (int j = 0; j < 4; j++) acc2[i][j] = 0ULL;

        for (int kb = 0; kb < NIN; kb += 32) {
#pragma unroll
            for (int it = 0; it < 4; it++) {
                int idx = t + it * 256;
                int r   = idx >> 3;
                int c4  = idx & 7;
                float4 v = *(const float4*)&X[(size_t)(m0 + r) * NIN + kb + c4 * 4];
                sm_As[c4 * 4 + 0][r] = v.x;
                sm_As[c4 * 4 + 1][r] = v.y;
                sm_As[c4 * 4 + 2][r] = v.z;
                sm_As[c4 * 4 + 3][r] = v.w;
            }
#pragma unroll
            for (int it = 0; it < 2; it++) {
                int idx = t + it * 256;
                int r   = idx >> 3;
                int c4  = idx & 7;
                float4 v = *(const float4*)&W_ih[(size_t)(n0 + r) * NIN + kb + c4 * 4];
                sm_Bs[c4 * 4 + 0][r] = v.x;
                sm_Bs[c4 * 4 + 1][r] = v.y;
                sm_Bs[c4 * 4 + 2][r] = v.z;
                sm_Bs[c4 * 4 + 3][r] = v.w;
            }
            __syncthreads();
#pragma unroll
            for (int k = 0; k < 32; k++) {
                const ulonglong2* ap = (const ulonglong2*)&sm_As[k][ty * 8];
                ulonglong2 av0 = ap[0];
                ulonglong2 av1 = ap[1];
                float4 bv = *(const float4*)&sm_Bs[k][tx * 4];
                unsigned long long bd0 = pack_dup(bv.x);
                unsigned long long bd1 = pack_dup(bv.y);
                unsigned long long bd2 = pack_dup(bv.z);
                unsigned long long bd3 = pack_dup(bv.w);
                FMA2(acc2[0][0], av0.x, bd0); FMA2(acc2[0][1], av0.x, bd1);
                FMA2(acc2[0][2], av0.x, bd2); FMA2(acc2[0][3], av0.x, bd3);
                FMA2(acc2[1][0], av0.y, bd0); FMA2(acc2[1][1], av0.y, bd1);
                FMA2(acc2[1][2], av0.y, bd2); FMA2(acc2[1][3], av0.y, bd3);
                FMA2(acc2[2][0], av1.x, bd0); FMA2(acc2[2][1], av1.x, bd1);
                FMA2(acc2[2][2], av1.x, bd2); FMA2(acc2[2][3], av1.x, bd3);
                FMA2(acc2[3][0], av1.y, bd0); FMA2(acc2[3][1], av1.y, bd1);
                FMA2(acc2[3][2], av1.y, bd2); FMA2(acc2[3][3], av1.y, bd3);
            }
            __syncthreads();
        }

        const int nbase = n0 + tx * 4;
        float4 bias;
        bias.x = b_ih[nbase + 0] + b_hh[nbase + 0];
        bias.y = b_ih[nbase + 1] + b_hh[nbase + 1];
        bias.z = b_ih[nbase + 2] + b_hh[nbase + 2];
        bias.w = b_ih[nbase + 3] + b_hh[nbase + 3];
#pragma unroll
        for (int mi = 0; mi < 4; mi++) {
            float2 c0 = unpack2(acc2[mi][0]);
            float2 c1 = unpack2(acc2[mi][1]);
            float2 c2 = unpack2(acc2[mi][2]);
            float2 c3 = unpack2(acc2[mi][3]);
            int mA = m0 + ty * 8 + 2 * mi;
            float4 v0 = { c0.x + bias.x, c1.x + bias.y, c2.x + bias.z, c3.x + bias.w };
            float4 v1 = { c0.y + bias.x, c1.y + bias.y, c2.y + bias.z, c3.y + bias.w };
            *(float4*)&g_xp[(size_t)mA * HID + nbase]       = v0;
            *(float4*)&g_xp[(size_t)(mA + 1) * HID + nbase] = v1;
        }

        __syncthreads();
        if (t == 0) {
            __threadfence();
            atomicAdd(&g_done[chunk], 1);
        }
        return;
    }

    // ===================== RECURRENCE (R2 verbatim + gate) =====================
    const uint32_t rank = blockIdx.x & 1;
    const int      b    = blockIdx.x >> 1;
    const int      k0   = rank << 7;

    // weights: W_hh[row t][k0 .. k0+127] -> 64 u64 regs
    unsigned long long w2[64];
    {
        const ulonglong2* wp = (const ulonglong2*)(W_hh + (size_t)t * HID + k0);
#pragma unroll
        for (int i = 0; i < 32; i++) {
            ulonglong2 v = wp[i];
            w2[2 * i]     = v.x;
            w2[2 * i + 1] = v.y;
        }
    }

    sm_h[0][t] = 0.f;
    if (t == 0) {
        asm volatile("mbarrier.init.shared.b64 [%0], 1;"
                     :: "r"(smem_u32(&sm_mbar[0])) : "memory");
        asm volatile("mbarrier.init.shared.b64 [%0], 1;"
                     :: "r"(smem_u32(&sm_mbar[1])) : "memory");
    }
    __syncthreads();
    asm volatile("barrier.cluster.arrive.aligned;" ::: "memory");
    asm volatile("barrier.cluster.wait.aligned;"   ::: "memory");

    const uint32_t peer  = rank ^ 1u;
    const uint32_t p_loc = smem_u32(&sm_p[0][0]);
    const uint32_t m_loc = smem_u32(&sm_mbar[0]);
    uint32_t p_rem, m_rem;
    asm("mapa.shared::cluster.u32 %0, %1, %2;"
        : "=r"(p_rem) : "r"(p_loc), "r"(peer));
    asm("mapa.shared::cluster.u32 %0, %1, %2;"
        : "=r"(m_rem) : "r"(m_loc), "r"(peer));

    // xp window (3 deep). Chunks 0..2 guaranteed by the head kernel.
    const float* xpb = g_xp + (size_t)b * HID + t;
    float xp0 = xpb[0];
    float xp1 = xpb[(size_t)1 * BATCH * HID];
    float xp2 = xpb[(size_t)2 * BATCH * HID];

    float* outp = out + (size_t)b * HID + t;
    const bool own = ((uint32_t)(t >> 7) == rank);
    int wm = HEAD_CHUNKS;                 // t0's flag watermark (tail only)

#pragma unroll 1
    for (int s = 0; s < SEQ; s++) {
        const uint32_t bufsel = (uint32_t)(s & 1);
        const uint32_t parity = (uint32_t)((s >> 1) & 1);

        // prefetch xp[s+3] (covered by the gate's 16-step lead)
        float xpn = 0.f;
        if (s + 3 < SEQ) xpn = xpb[(size_t)(s + 3) * BATCH * HID];

        // ---- dot over own k-half: 32 LDS.128 + 64 FFMA2 ----
        const ulonglong2* hp = (const ulonglong2*)(&sm_h[bufsel][0] + k0);
        unsigned long long a0 = 0ULL, a1 = 0ULL, a2 = 0ULL, a3 = 0ULL;
#pragma unroll
        for (int i = 0; i < 16; i++) {
            ulonglong2 h01 = hp[2 * i];
            ulonglong2 h23 = hp[2 * i + 1];
            FMA2(a0, w2[4 * i + 0], h01.x);
            FMA2(a1, w2[4 * i + 1], h01.y);
            FMA2(a2, w2[4 * i + 2], h23.x);
            FMA2(a3, w2[4 * i + 3], h23.y);
        }
        float2 f0 = unpack2(a0), f1 = unpack2(a1);
        float2 f2 = unpack2(a2), f3 = unpack2(a3);
        float mine = ((f0.x + f0.y) + (f1.x + f1.y))
                   + ((f2.x + f2.y) + (f3.x + f3.y));

        // ---- send partial to peer (all 256 threads; R2-proven) ----
        asm volatile(
            "st.async.shared::cluster.mbarrier::complete_tx::bytes.b32 "
            "[%0], %1, [%2];"
            :: "r"(p_rem + (bufsel << 10) + ((uint32_t)t << 2)),
               "r"(__float_as_uint(mine)),
               "r"(m_rem + bufsel * 8)
            : "memory");

        if (t == 0) {
            asm volatile(
                "mbarrier.arrive.expect_tx.shared.b64 _, [%0], 1024;"
                :: "r"(m_loc + bufsel * 8) : "memory");
            // flag gate: keep 16-step lead over the xp prefetches (tail only)
            if ((s & 15) == 0) {
                int need = (s + 35) >> 1;
                if (need > PROJ_CHUNKS - 1) need = PROJ_CHUNKS - 1;
                while (wm <= need) {
                    if (ld_acquire_gpu(&g_done[wm]) >= 4) wm++;
                }
            }
        }

        mbar_wait(m_loc + bufsel * 8, parity);

        // ---- combine (deterministic order), tanh, publish ----
        float theirs = sm_p[bufsel][t];
        float lo = rank ? theirs : mine;
        float hi = rank ? mine   : theirs;
        float hv = tanhf(xp0 + (lo + hi));
        if (own) {
            sm_h[bufsel ^ 1u][t] = hv;
            outp[(size_t)s * BATCH * HID] = hv;
        }

        xp0 = xp1; xp1 = xp2; xp2 = xpn;
        __syncthreads();
    }

    asm volatile("barrier.cluster.arrive.aligned;" ::: "memory");
    asm volatile("barrier.cluster.wait.aligned;"   ::: "memory");
}

// ---------------------------------------------------------------------------
extern "C" void kernel_launch(void* const* d_in, const int* in_sizes, int n_in,
                              void* d_out, int out_size)
{
    const float* input = (const float*)d_in[0];   // [SEQ, BATCH, NIN]
    const float* W_ih  = (const float*)d_in[1];   // [HID, NIN]
    const float* W_hh  = (const float*)d_in[2];   // [HID, HID]
    const float* b_ih  = (const float*)d_in[3];   // [HID]
    const float* b_hh  = (const float*)d_in[4];   // [HID]
    float* out = (float*)d_out;                   // [SEQ*BATCH, HID]

    // 0) zero the tail-completion flags
    reset_kernel<<<1, 256>>>();

    // 1) projection HEAD: chunks [0, 704) on the full chip (~250us)
    dim3 hgrid(HEAD_CHUNKS, 4);
    proj_kernel<<<hgrid, 256>>>(input, W_ih, b_ih, b_hh);

    // 2) fused: rnn (128 CTAs, 64 clusters) + projection TAIL (chunks 704..1023)
    fused_kernel<<<TOTAL_BLOCKS, 256>>>(input, W_ih, W_hh, b_ih, b_hh, out);
}